// round 3
// baseline (speedup 1.0000x reference)
#include <cuda_runtime.h>

// Problem constants
#define H_   768
#define NCT_ 4096
#define NL_  8921
#define NN_  4

// Accumulator scratch (no cudaMalloc allowed)
__device__ float g_G[8 * H_];  // column sums of reshaped label_weights per l-group
__device__ float g_E[8 * H_];  // per-chunk column sums of encoding

static constexpr int TILE_ROWS = 32;
static constexpr int NB_LW = (NL_ + TILE_ROWS - 1) / TILE_ROWS;  // 279
static constexpr int NB_EN = NCT_ / TILE_ROWS;                   // 128

__global__ void zero_kernel() {
    int i = blockIdx.x * blockDim.x + threadIdx.x;
    if (i < 8 * H_) { g_G[i] = 0.0f; g_E[i] = 0.0f; }
}

// One kernel streams both label_weights (as its (8921,768) flat view) and
// encoding (4096,768), computing segment column-sums with at most one
// segment boundary per 32-row tile. 192 threads x float4 = 768 columns.
__global__ __launch_bounds__(192) void reduce_kernel(
    const float4* __restrict__ lw4, const float4* __restrict__ enc4)
{
    const int t = threadIdx.x;
    int b = blockIdx.x;

    const float4* src;
    float* dst;
    int row0, rend, seg0, seg1, split;

    if (b < NB_LW) {
        row0 = b * TILE_ROWS;
        rend = min(row0 + TILE_ROWS, NL_);
        src = lw4; dst = g_G;
        const int LB[7] = {1113, 2229, 3344, 4459, 5574, 6689, 7804};
        seg0 = 0; seg1 = 0;
        #pragma unroll
        for (int i = 0; i < 7; i++) {
            seg0 += (row0 >= LB[i]);
            seg1 += (rend - 1 >= LB[i]);
        }
        split = (seg1 == seg0) ? rend : LB[seg0];
    } else {
        int b2 = b - NB_LW;
        row0 = b2 * TILE_ROWS;
        rend = row0 + TILE_ROWS;
        src = enc4; dst = g_E;
        seg0 = row0 >> 9;   // 512 rows per chunk; tiles are aligned -> no split
        seg1 = seg0;
        split = rend;
    }

    float ax = 0.f, ay = 0.f, az = 0.f, aw = 0.f;
    int r = row0;
    #pragma unroll 4
    for (; r < split; ++r) {
        float4 v = __ldg(&src[r * (H_ / 4) + t]);
        ax += v.x; ay += v.y; az += v.z; aw += v.w;
    }
    {
        float* p = dst + seg0 * H_ + t * 4;
        atomicAdd(p + 0, ax); atomicAdd(p + 1, ay);
        atomicAdd(p + 2, az); atomicAdd(p + 3, aw);
    }
    if (r < rend) {
        ax = ay = az = aw = 0.f;
        #pragma unroll 4
        for (; r < rend; ++r) {
            float4 v = __ldg(&src[r * (H_ / 4) + t]);
            ax += v.x; ay += v.y; az += v.z; aw += v.w;
        }
        float* p = dst + seg1 * H_ + t * 4;
        atomicAdd(p + 0, ax); atomicAdd(p + 1, ay);
        atomicAdd(p + 2, az); atomicAdd(p + 3, aw);
    }
}

// Final combine: 4 blocks (one per note) x 768 threads (one per h).
__global__ __launch_bounds__(768) void finalize_kernel(
    const float* __restrict__ lw, const void* __restrict__ ids_raw,
    float* __restrict__ out)
{
    const int h = threadIdx.x;
    const int n = blockIdx.x;

    // note_end_chunk_ids: detect int64 vs int32 (values are small nonneg, sorted)
    const int* i32 = (const int*)ids_raw;
    int id[4];
    if (i32[1] == 0 && i32[3] == 0) {           // int64 layout: [v0,0,v1,0,...]
        const long long* i64 = (const long long*)ids_raw;
        #pragma unroll
        for (int i = 0; i < 4; i++) id[i] = (int)i64[i];
    } else {                                     // int32 layout
        #pragma unroll
        for (int i = 0; i < 4; i++) id[i] = i32[i];
    }
    const int idn = id[n];

    // w(n,c): softmax over notes of the (0 / -1e9) mask, chunk-piecewise.
    float wn[8];
    #pragma unroll
    for (int c = 0; c < 8; c++) {
        int k = (id[0] < c) + (id[1] < c) + (id[2] < c) + (id[3] < c);
        wn[c] = (k == 0) ? 0.25f : ((idn < c) ? (1.0f / (float)k) : 0.0f);
    }

    // Prefix sums of encoding chunk sums: Pm[m] = P[512*m][h], Pm[8] = Ptot
    float Pm[9];
    Pm[0] = 0.0f;
    #pragma unroll
    for (int m = 1; m <= 8; m++) Pm[m] = Pm[m - 1] + g_E[(m - 1) * H_ + h];
    const float Ptot = Pm[8];

    float gacc = 0.0f;
    #pragma unroll
    for (int c = 0; c < 8; c++) gacc += wn[c] * g_G[c * H_ + h];
    float score = Ptot * gacc;

    // 15 l-runs that straddle a weights-row chunk boundary (compile-time).
    // d = w(n,cA) - w(n,cA+1); factor P[s] with s encoded as m (8 == Ptot).
    const int SL[15] = {1113,1114,1115, 2229,2230, 3344,3345, 4459,4460,
                        5574,5575, 6689,6690, 7804,7805};
    const int SC[15] = {0,0,0, 1,1, 2,2, 3,3, 4,4, 5,5, 6,6};
    const int SM[15] = {8,8,1, 8,2, 8,3, 8,4, 8,5, 8,6, 8,7};
    #pragma unroll
    for (int j = 0; j < 15; j++) {
        float d = wn[SC[j]] - wn[SC[j] + 1];
        score += d * __ldg(&lw[SL[j] * H_ + h]) * Pm[SM[j]];
    }

    out[n * H_ + h] = 1.0f / (1.0f + expf(-score));
}

extern "C" void kernel_launch(void* const* d_in, const int* in_sizes, int n_in,
                              void* d_out, int out_size) {
    const float* encoding      = (const float*)d_in[0];
    // d_in[1] = label_queries: provably unused (softmax over notes cancels it)
    const float* label_weights = (const float*)d_in[2];
    const void*  ids           = d_in[3];
    float* out = (float*)d_out;

    zero_kernel<<<(8 * H_ + 255) / 256, 256>>>();
    reduce_kernel<<<NB_LW + NB_EN, 192>>>((const float4*)label_weights,
                                          (const float4*)encoding);
    finalize_kernel<<<NN_, H_>>>(label_weights, ids, out);
}